// round 15
// baseline (speedup 1.0000x reference)
#include <cuda_runtime.h>
#include <cuda_fp16.h>

#define C 64
#define MAXN 50000
#define MAXE 800000

// Scratch (allocation-free, graph-safe). g_cnt/g_total are zero at module load
// and re-zeroed by k_aggrelu's epilogue every invocation (deterministic replay).
__device__ int   g_cnt[MAXN];                    // per-target degree
__device__ int   g_off[MAXN];                    // CSR segment starts (unordered)
__device__ float g_dis[MAXN];                    // deg_inv_sqrt
__device__ int   g_rank[MAXE];                   // edge's rank within its target
__device__ int   g_srcid[MAXE];                  // CSR: source id per slot
__device__ int   g_total;                        // global segment cursor
__device__ __align__(16) __half2 g_h[MAXN * C / 2];  // h' = dis[n]*(x@W^T)[n], fp16

// Degree histogram, 4 independent edges per thread (MLP=4).
// Thread t handles edges t, t+T, t+2T, t+3T (coalesced per batch).
__global__ void k_deg(const int* __restrict__ tgt, int E, int T) {
    int t = blockIdx.x * blockDim.x + threadIdx.x;
    if (t >= T) return;
    int i0 = t, i1 = t + T, i2 = t + 2 * T, i3 = t + 3 * T;
    int d0 = tgt[i0];
    int d1 = (i1 < E) ? tgt[i1] : -1;
    int d2 = (i2 < E) ? tgt[i2] : -1;
    int d3 = (i3 < E) ? tgt[i3] : -1;
    int r0 = atomicAdd(&g_cnt[d0], 1);
    int r1 = (d1 >= 0) ? atomicAdd(&g_cnt[d1], 1) : 0;
    int r2 = (d2 >= 0) ? atomicAdd(&g_cnt[d2], 1) : 0;
    int r3 = (d3 >= 0) ? atomicAdd(&g_cnt[d3], 1) : 0;
    g_rank[i0] = r0;
    if (d1 >= 0) g_rank[i1] = r1;
    if (d2 >= 0) g_rank[i2] = r2;
    if (d3 >= 0) g_rank[i3] = r3;
}

// Fused: CSR offsets (warp-scan + cursor atomic) + deg_inv_sqrt + h' = dis*(x@W^T).
// GEMM mainloop uses packed fma.rn.f32x2; epilogue packs to fp16 (half the write).
__global__ void __launch_bounds__(64) k_h(const float* __restrict__ x,
                                          const float* __restrict__ W, int N) {
    __shared__ __align__(16) float Ws[C * C];    // Ws[k*64 + j] = W[j*64 + k]
    __shared__ float As[64][C + 1];
    __shared__ float Ds[64];
    int tid = threadIdx.x;
    int lane = tid & 31;
    int node = blockIdx.x * 64 + tid;

    // Offsets + dis (scan-free global cursor; segment order unimportant).
    {
        int c = (node < N) ? g_cnt[node] : 0;
        int v = c;
        #pragma unroll
        for (int d = 1; d < 32; d <<= 1) {
            int u = __shfl_up_sync(0xffffffffu, v, d);
            if (lane >= d) v += u;
        }
        int wtot = __shfl_sync(0xffffffffu, v, 31);
        int wbase = 0;
        if (lane == 31) wbase = atomicAdd(&g_total, wtot);
        wbase = __shfl_sync(0xffffffffu, wbase, 31);
        float dis = rsqrtf(fmaxf((float)c, 1.0f));
        if (node < N) {
            g_off[node] = wbase + v - c;
            g_dis[node] = dis;
        }
        Ds[tid] = dis;
    }

    for (int idx = tid; idx < C * C; idx += 64) {
        int j = idx >> 6, k = idx & 63;
        Ws[k * C + j] = W[idx];
    }
    int base = blockIdx.x * 64;
    for (int idx = tid; idx < 64 * 16; idx += 64) {
        int i = idx >> 4, j4 = idx & 15;
        int r = base + i;
        float4 v = (r < N) ? ((const float4*)(x + (size_t)r * C))[j4]
                           : make_float4(0.f, 0.f, 0.f, 0.f);
        As[i][j4 * 4 + 0] = v.x;
        As[i][j4 * 4 + 1] = v.y;
        As[i][j4 * 4 + 2] = v.z;
        As[i][j4 * 4 + 3] = v.w;
    }
    __syncthreads();

    // Packed accumulators: acc2[p] holds outputs (2p, 2p+1) as f32x2.
    unsigned long long acc2[C / 2];
    #pragma unroll
    for (int p = 0; p < C / 2; p++) acc2[p] = 0ULL;

    for (int k = 0; k < C; k++) {
        float ak = As[tid][k];
        unsigned long long ak2;
        asm("mov.b64 %0, {%1, %1};" : "=l"(ak2) : "f"(ak));
        const ulonglong2* wr = (const ulonglong2*)(Ws + k * C);  // 2 packed pairs / 16B
        #pragma unroll
        for (int q = 0; q < C / 4; q++) {
            ulonglong2 w2 = wr[q];
            asm("fma.rn.f32x2 %0, %1, %2, %0;" : "+l"(acc2[2 * q])     : "l"(w2.x), "l"(ak2));
            asm("fma.rn.f32x2 %0, %1, %2, %0;" : "+l"(acc2[2 * q + 1]) : "l"(w2.y), "l"(ak2));
        }
    }

    if (node < N) {
        float dis = Ds[tid];
        uint4* o = (uint4*)(g_h + (size_t)node * (C / 2));
        #pragma unroll
        for (int q = 0; q < 8; q++) {            // 8 x uint4 = 32 half2 = 64 halfs
            unsigned int hw[4];
            #pragma unroll
            for (int r = 0; r < 4; r++) {
                float e0, e1;
                asm("mov.b64 {%0, %1}, %2;" : "=f"(e0), "=f"(e1) : "l"(acc2[4 * q + r]));
                __half2 hv = __floats2half2_rn(dis * e0, dis * e1);
                hw[r] = *(unsigned int*)&hv;
            }
            o[q] = make_uint4(hw[0], hw[1], hw[2], hw[3]);
        }
    }
}

// CSR fill, no atomics, 4 independent edges per thread (MLP=4).
__global__ void k_fill(const int* __restrict__ src, const int* __restrict__ tgt,
                       int E, int T) {
    int t = blockIdx.x * blockDim.x + threadIdx.x;
    if (t >= T) return;
    int i0 = t, i1 = t + T, i2 = t + 2 * T, i3 = t + 3 * T;
    int d0 = tgt[i0];
    int d1 = (i1 < E) ? tgt[i1] : -1;
    int d2 = (i2 < E) ? tgt[i2] : -1;
    int d3 = (i3 < E) ? tgt[i3] : -1;
    int s0 = src[i0];
    int s1 = (d1 >= 0) ? src[i1] : 0;
    int s2 = (d2 >= 0) ? src[i2] : 0;
    int s3 = (d3 >= 0) ? src[i3] : 0;
    int r0 = g_rank[i0];
    int r1 = (d1 >= 0) ? g_rank[i1] : 0;
    int r2 = (d2 >= 0) ? g_rank[i2] : 0;
    int r3 = (d3 >= 0) ? g_rank[i3] : 0;
    int o0 = g_off[d0];
    int o1 = (d1 >= 0) ? g_off[d1] : 0;
    int o2 = (d2 >= 0) ? g_off[d2] : 0;
    int o3 = (d3 >= 0) ? g_off[d3] : 0;
    g_srcid[o0 + r0] = s0;
    if (d1 >= 0) g_srcid[o1 + r1] = s1;
    if (d2 >= 0) g_srcid[o2 + r2] = s2;
    if (d3 >= 0) g_srcid[o3 + r3] = s3;
}

// Aggregate fp16 h' over CSR + dis[tgt] + bias + relu, writing d_out (fp32).
// One warp per node: each row gather = 32 lanes x 4B = ONE 128B line.
// fp32 accumulation; unroll-8 gather MLP. Epilogue re-zeroes g_cnt/g_total.
__global__ void k_aggrelu(const float* __restrict__ bias, float* __restrict__ out, int N) {
    int w = (blockIdx.x * blockDim.x + threadIdx.x) >> 5;
    int lane = threadIdx.x & 31;
    if (w >= N) return;
    int off = g_off[w];
    int cnt = g_cnt[w];
    const __half2* hp = g_h + lane;            // lane's channel pair within a row
    float a0 = 0.0f, a1 = 0.0f;
    int i = 0;
    for (; i + 8 <= cnt; i += 8) {
        int s0 = g_srcid[off + i];
        int s1 = g_srcid[off + i + 1];
        int s2 = g_srcid[off + i + 2];
        int s3 = g_srcid[off + i + 3];
        int s4 = g_srcid[off + i + 4];
        int s5 = g_srcid[off + i + 5];
        int s6 = g_srcid[off + i + 6];
        int s7 = g_srcid[off + i + 7];
        __half2 v0 = hp[(size_t)s0 * (C / 2)];
        __half2 v1 = hp[(size_t)s1 * (C / 2)];
        __half2 v2 = hp[(size_t)s2 * (C / 2)];
        __half2 v3 = hp[(size_t)s3 * (C / 2)];
        __half2 v4 = hp[(size_t)s4 * (C / 2)];
        __half2 v5 = hp[(size_t)s5 * (C / 2)];
        __half2 v6 = hp[(size_t)s6 * (C / 2)];
        __half2 v7 = hp[(size_t)s7 * (C / 2)];
        float2 f0 = __half22float2(v0);
        float2 f1 = __half22float2(v1);
        float2 f2 = __half22float2(v2);
        float2 f3 = __half22float2(v3);
        float2 f4 = __half22float2(v4);
        float2 f5 = __half22float2(v5);
        float2 f6 = __half22float2(v6);
        float2 f7 = __half22float2(v7);
        a0 += f0.x + f1.x + f2.x + f3.x + f4.x + f5.x + f6.x + f7.x;
        a1 += f0.y + f1.y + f2.y + f3.y + f4.y + f5.y + f6.y + f7.y;
    }
    for (; i + 2 <= cnt; i += 2) {
        float2 f0 = __half22float2(hp[(size_t)g_srcid[off + i] * (C / 2)]);
        float2 f1 = __half22float2(hp[(size_t)g_srcid[off + i + 1] * (C / 2)]);
        a0 += f0.x + f1.x;
        a1 += f0.y + f1.y;
    }
    if (i < cnt) {
        float2 f = __half22float2(hp[(size_t)g_srcid[off + i] * (C / 2)]);
        a0 += f.x;
        a1 += f.y;
    }

    float dn = g_dis[w];
    float2 bb = *(const float2*)(bias + lane * 2);
    float2 r;
    r.x = fmaxf(a0 * dn + bb.x, 0.0f);
    r.y = fmaxf(a1 * dn + bb.y, 0.0f);
    *(float2*)(out + (size_t)w * C + lane * 2) = r;

    // Restore zeros for next invocation (own node only).
    if (lane == 0) {
        g_cnt[w] = 0;
        if (w == 0) g_total = 0;
    }
}

extern "C" void kernel_launch(void* const* d_in, const int* in_sizes, int n_in,
                              void* d_out, int out_size) {
    const float* x   = (const float*)d_in[0];
    const int*   ei  = (const int*)d_in[1];     // int32, [2, E] row-major
    const float* W   = (const float*)d_in[2];
    const float* b   = (const float*)d_in[3];
    float*       out = (float*)d_out;

    int N = in_sizes[0] / C;     // 50000
    int E = in_sizes[1] / 2;     // 800000
    const int* src = ei;
    const int* tgt = ei + E;

    int T = (E + 3) / 4;         // threads for 4-edge-per-thread kernels

    k_deg<<<(T + 255) / 256, 256>>>(tgt, E, T);
    k_h<<<(N + 63) / 64, 64>>>(x, W, N);          // offsets + dis + scaled GEMM
    k_fill<<<(T + 255) / 256, 256>>>(src, tgt, E, T);

    long long TT = (long long)N * 32;
    k_aggrelu<<<(int)((TT + 255) / 256), 256>>>(b, out, N);
}